// round 15
// baseline (speedup 1.0000x reference)
#include <cuda_runtime.h>
#include <math.h>

#define BCn 256

static __device__ float2 g_Xf[BCn*32*32*32];   // [bc][p][k][i]
static __device__ float2 g_Wt[2*32*32*32];     // [li][k][o][i]
static __device__ float  g_h [BCn*32*128*32];  // [bc][p][d][s]
static __device__ float  g_enc[BCn*4096];
static __device__ float  g_xn [BCn*4096];
static __device__ float  g_Cm [BCn*1024];
static __device__ float  g_mu[BCn], g_sd[BCn];

__device__ __forceinline__ unsigned long long pk2(float x, float y) {
  unsigned long long r; asm("mov.b64 %0,{%1,%2};" : "=l"(r) : "f"(x), "f"(y)); return r;
}
__device__ __forceinline__ unsigned long long fma2(unsigned long long a, unsigned long long b, unsigned long long c) {
  unsigned long long d; asm("fma.rn.f32x2 %0,%1,%2,%3;" : "=l"(d) : "l"(a), "l"(b), "l"(c)); return d;
}

struct SMS {
  float enc[4096], xn[4096], del[4096];
  float xw[72*129];
  float dw[128*9];
  float db[128], gg[128], bb[128];
  float dbc[32*80];
};
struct SMD {
  float2 sd[4*64*32];   // [tok][dp][i] = {su, dv}; dp=0 row = {h0, h64}
  float2 tw[64*32];     // [dp][k] = {cos, -sin}
};
struct SMX {
  float2 Wk[32*34];     // [o][i], pad 34 — FIRST so 16B loads are aligned
  float2 trigH[65*33];
  float2 G[16*33];
  unsigned long long Cm2[16*32];
  float  dpv[128];
};

__global__ void __launch_bounds__(512) kA(const float* __restrict__ x) {
  __shared__ float xs[512];
  __shared__ float red[34], red2[16];
  int t = threadIdx.x, bc = blockIdx.x, b = bc >> 5, c = bc & 31;
  float xv = x[(b * 512 + t) * 32 + c];
  float s1 = xv, s2 = xv * xv;
  for (int o = 16; o; o >>= 1) {
    s1 += __shfl_xor_sync(0xFFFFFFFFu, s1, o);
    s2 += __shfl_xor_sync(0xFFFFFFFFu, s2, o);
  }
  if ((t & 31) == 0) { red[t >> 5] = s1; red2[t >> 5] = s2; }
  __syncthreads();
  if (t == 0) {
    float a = 0.f, q = 0.f;
    for (int i = 0; i < 16; i++) { a += red[i]; q += red2[i]; }
    float mu = a * (1.f / 512.f);
    float sd = sqrtf(q * (1.f / 512.f) - mu * mu + 1e-5f);
    red[32] = mu; red[33] = sd;
    g_mu[bc] = mu; g_sd[bc] = sd;
  }
  __syncthreads();
  xs[t] = (xv - red[32]) / red[33];
  __syncthreads();
  for (int e = t; e < 4096; e += 512) {
    int p = e >> 7, d = e & 127, m = d >> 4, pl = d & 15;
    int t0 = p * 16 + pl;
    g_enc[bc * 4096 + e] = (t0 >= 7) ? xs[t0 - 7 + m] : 0.f;
  }
}

__global__ void krepack(const float* __restrict__ Kr, const float* __restrict__ Ki) {
  int idx = blockIdx.x * 256 + threadIdx.x;
  int k = idx & 31, o = (idx >> 5) & 31, i = (idx >> 10) & 31, li = idx >> 15;
  g_Wt[((li * 32 + k) * 32 + o) * 32 + i] = make_float2(Kr[idx], Ki[idx]);
}

__global__ void __launch_bounds__(512, 1) kscan(
    int li, const float* __restrict__ xw_g, const float* __restrict__ dw_g,
    const float* __restrict__ db_g, const float* __restrict__ Al_g,
    const float* __restrict__ lng, const float* __restrict__ lnb) {
  extern __shared__ __align__(16) unsigned char raw[];
  SMS* sm = reinterpret_cast<SMS*>(raw);
  int t = threadIdx.x, lane = t & 31, w = t >> 5, bc = blockIdx.x;

  for (int e = t; e < 9216; e += 512) {
    int r = e >> 7, d = e & 127;
    sm->xw[r * 129 + d] = xw_g[li * 9216 + e];
  }
  for (int e = t; e < 1024; e += 512) {
    int d = e >> 3, r = e & 7;
    sm->dw[d * 9 + r] = dw_g[li * 1024 + e];
  }
  if (t < 128) {
    sm->db[t] = db_g[li * 128 + t];
    sm->gg[t] = lng[li * 128 + t];
    sm->bb[t] = lnb[li * 128 + t];
  }
  for (int e = t; e < 4096; e += 512) sm->enc[e] = g_enc[bc * 4096 + e];
  __syncthreads();

  for (int pp = 0; pp < 2; pp++) {
    int p = w * 2 + pp;
    float v[4], s = 0.f, q = 0.f;
    for (int j = 0; j < 4; j++) {
      v[j] = sm->enc[p * 128 + lane + 32 * j];
      s += v[j]; q += v[j] * v[j];
    }
    for (int o = 16; o; o >>= 1) {
      s += __shfl_xor_sync(0xFFFFFFFFu, s, o);
      q += __shfl_xor_sync(0xFFFFFFFFu, q, o);
    }
    float mu = s * (1.f / 128.f);
    float rs = rsqrtf(q * (1.f / 128.f) - mu * mu + 1e-5f);
    for (int j = 0; j < 4; j++) {
      int d = lane + 32 * j;
      sm->xn[p * 128 + d] = (v[j] - mu) * rs * sm->gg[d] + sm->bb[d];
    }
  }
  __syncthreads();

  {
    int p = t >> 4, rt = t & 15;
    float a0 = 0, a1 = 0, a2 = 0, a3 = 0, a4 = 0;
    const float* xp = &sm->xn[p * 128];
    for (int d = 0; d < 128; d++) {
      float xv = xp[d];
      a0 += xv * sm->xw[rt * 129 + d];
      a1 += xv * sm->xw[(rt + 16) * 129 + d];
      a2 += xv * sm->xw[(rt + 32) * 129 + d];
      a3 += xv * sm->xw[(rt + 48) * 129 + d];
      if (rt < 8) a4 += xv * sm->xw[(rt + 64) * 129 + d];
    }
    sm->dbc[p * 80 + rt] = a0;
    sm->dbc[p * 80 + rt + 16] = a1;
    sm->dbc[p * 80 + rt + 32] = a2;
    sm->dbc[p * 80 + rt + 48] = a3;
    if (rt < 8) sm->dbc[p * 80 + rt + 64] = a4;
  }
  __syncthreads();

  {
    int p = t >> 4, d0 = (t & 15) * 8;
    for (int d = d0; d < d0 + 8; d++) {
      float a = sm->db[d];
      for (int r = 0; r < 8; r++) a += sm->dbc[p * 80 + r] * sm->dw[d * 9 + r];
      sm->del[p * 128 + d] = (a > 20.f) ? a : log1pf(__expf(a));
    }
    int s2 = (t & 15) * 2;
    g_Cm[bc * 1024 + p * 32 + s2]     = sm->dbc[p * 80 + 40 + s2];
    g_Cm[bc * 1024 + p * 32 + s2 + 1] = sm->dbc[p * 80 + 40 + s2 + 1];
  }
  __syncthreads();

  // scan: thread owns d = t>>2, 8 states; no barriers; h -> global
  int dd = t >> 2, s0 = (t & 3) * 8;
  float A[8], hreg[8];
  for (int q = 0; q < 8; q++) {
    A[q] = -__expf(Al_g[li * 4096 + dd * 32 + s0 + q]);
    hreg[q] = 0.f;
  }
  for (int p = 0; p < 32; p++) {
    float dl = sm->del[p * 128 + dd];
    float bx = dl * sm->xn[p * 128 + dd];
#pragma unroll
    for (int q = 0; q < 8; q++)
      hreg[q] = __expf(dl * A[q]) * hreg[q] + bx * sm->dbc[p * 80 + 8 + s0 + q];
    float* hb = &g_h[((bc * 32 + p) * 128 + dd) * 32 + s0];
    *reinterpret_cast<float4*>(hb)     = make_float4(hreg[0], hreg[1], hreg[2], hreg[3]);
    *reinterpret_cast<float4*>(hb + 4) = make_float4(hreg[4], hreg[5], hreg[6], hreg[7]);
  }
  for (int e = t; e < 4096; e += 512) g_xn[bc * 4096 + e] = sm->xn[e];
}

__global__ void __launch_bounds__(512, 2) kDFT() {
  extern __shared__ __align__(16) unsigned char raw[];
  SMD* sm = reinterpret_cast<SMD*>(raw);
  int t = threadIdx.x, bc = blockIdx.x, p0 = blockIdx.y * 4;

  for (int e = t; e < 2048; e += 512) {
    int dp = e >> 5, k = e & 31;
    float sv, cv;
    sincospif((float)(dp * k) * (1.0f / 64.0f), &sv, &cv);
    sm->tw[e] = make_float2(cv, -sv);
  }
#pragma unroll
  for (int j = 0; j < 16; j++) {
    int e = t + 512 * j;                // 8192 = 4 tok * 64 dp * 32 s
    int tok = e >> 11, r = e & 2047, dp = r >> 5, s = r & 31;
    const float* hb = &g_h[((bc * 32 + p0 + tok) * 128) * 32];
    float su, dv;
    if (dp == 0) { su = hb[s]; dv = hb[64 * 32 + s]; }
    else {
      float a = hb[dp * 32 + s], b2 = hb[(128 - dp) * 32 + s];
      su = a + b2; dv = a - b2;
    }
    sm->sd[tok * 2048 + dp * 32 + s] = make_float2(su, dv);
  }
  __syncthreads();

  int tok = t >> 7, tt = t & 127, k = tt >> 2, iq = tt & 3;
  const float2* sdb = &sm->sd[tok * 2048];
  float sgn = (k & 1) ? -1.f : 1.f;
  unsigned long long acc[8];
#pragma unroll
  for (int m = 0; m < 8; m++) {
    float2 s0v = sdb[iq * 8 + m];       // dp=0 row: {h0, h64}
    acc[m] = pk2(sgn * s0v.y, 0.f);
  }
#pragma unroll 8
  for (int dp = 0; dp < 64; dp++) {
    unsigned long long twv = *reinterpret_cast<const unsigned long long*>(&sm->tw[dp * 32 + k]);
    const ulonglong2* sp = reinterpret_cast<const ulonglong2*>(&sdb[dp * 32 + iq * 8]);
    ulonglong2 sa = sp[0], sb = sp[1], sc = sp[2], sdq = sp[3];
    acc[0] = fma2(sa.x, twv, acc[0]); acc[1] = fma2(sa.y, twv, acc[1]);
    acc[2] = fma2(sb.x, twv, acc[2]); acc[3] = fma2(sb.y, twv, acc[3]);
    acc[4] = fma2(sc.x, twv, acc[4]); acc[5] = fma2(sc.y, twv, acc[5]);
    acc[6] = fma2(sdq.x, twv, acc[6]); acc[7] = fma2(sdq.y, twv, acc[7]);
  }
  ulonglong2* dst = reinterpret_cast<ulonglong2*>(
      &g_Xf[((bc * 32 + p0 + tok) * 32 + k) * 32 + iq * 8]);
  dst[0] = make_ulonglong2(acc[0], acc[1]);
  dst[1] = make_ulonglong2(acc[2], acc[3]);
  dst[2] = make_ulonglong2(acc[4], acc[5]);
  dst[3] = make_ulonglong2(acc[6], acc[7]);
}

__global__ void __launch_bounds__(256, 3) kmix(int li, const float* __restrict__ Dp_g) {
  extern __shared__ __align__(16) unsigned char raw[];
  SMX* sm = reinterpret_cast<SMX*>(raw);
  int t = threadIdx.x, bc = blockIdx.x, pbase = blockIdx.y * 16;

  for (int e = t; e < 2145; e += 256) {
    int d = e / 33, k = e % 33;
    if (k < 32) {
      float sv, cv;
      sincospif((float)(d * k) * (1.0f / 64.0f), &sv, &cv);
      sm->trigH[d * 33 + k] = make_float2(cv, -sv);
    }
  }
  for (int e = t; e < 512; e += 256) {
    float c = g_Cm[bc * 1024 + (pbase + (e >> 5)) * 32 + (e & 31)];
    sm->Cm2[e] = pk2(c, c);
  }
  if (t < 128) sm->dpv[t] = Dp_g[li * 128 + t];
  __syncthreads();

  int pl = t >> 4, i0 = (t & 15) * 2, p = pbase + pl;
  for (int k = 0; k < 32; k++) {
    const float2* src = &g_Wt[(li * 32 + k) * 1024];
    for (int e = t; e < 1024; e += 256) {
      int o = e >> 5, i = e & 31;
      sm->Wk[o * 34 + i] = src[e];
    }
    __syncthreads();
    unsigned long long V2a = 0, V2b = 0;
    for (int o = 0; o < 32; o++) {
      unsigned long long cm = sm->Cm2[pl * 32 + o];
      ulonglong2 wv = *reinterpret_cast<const ulonglong2*>(&sm->Wk[o * 34 + i0]);
      V2a = fma2(wv.x, cm, V2a);
      V2b = fma2(wv.y, cm, V2b);
    }
    float2 Va = *reinterpret_cast<float2*>(&V2a);
    float2 Vb = *reinterpret_cast<float2*>(&V2b);
    float4 xa = *reinterpret_cast<const float4*>(&g_Xf[((bc * 32 + p) * 32 + k) * 32 + i0]);
    float2 g;
    g.x = xa.x * Va.x - xa.y * Va.y + xa.z * Vb.x - xa.w * Vb.y;
    g.y = xa.x * Va.y + xa.y * Va.x + xa.z * Vb.y + xa.w * Vb.x;
    for (int o = 1; o < 16; o <<= 1) {
      g.x += __shfl_xor_sync(0xFFFFFFFFu, g.x, o);
      g.y += __shfl_xor_sync(0xFFFFFFFFu, g.y, o);
    }
    if ((t & 15) == 0) sm->G[pl * 33 + k] = g;
    __syncthreads();
  }

  int j = t & 15;
  float g0 = sm->G[pl * 33].x;
  for (int m = 0; m < 4; m++) {
    int dp = j * 4 + m;
    float accC = g0, accS = 0.f;
    for (int k = 1; k < 32; k++) {
      float2 gk = sm->G[pl * 33 + k];
      float2 tp = sm->trigH[dp * 33 + k];
      accC += 2.f * gk.x * tp.x;
      accS += 2.f * gk.y * tp.y;
    }
    int e = p * 128 + dp;
    g_enc[bc * 4096 + e] += (accC + accS) * (1.f / 128.f) + sm->dpv[dp] * g_xn[bc * 4096 + e];
    if (dp >= 1) {
      int d2 = 128 - dp, e2 = p * 128 + d2;
      g_enc[bc * 4096 + e2] += (accC - accS) * (1.f / 128.f) + sm->dpv[d2] * g_xn[bc * 4096 + e2];
    }
  }
  if (j == 0) {
    float acc = g0;
    for (int k = 1; k < 32; k++)
      acc += 2.f * sm->G[pl * 33 + k].x * ((k & 1) ? -1.f : 1.f);
    int e = p * 128 + 64;
    g_enc[bc * 4096 + e] += acc * (1.f / 128.f) + sm->dpv[64] * g_xn[bc * 4096 + e];
  }
}

__global__ void __launch_bounds__(128) khead(const float* __restrict__ ow,
                                             const float* __restrict__ ob,
                                             float* __restrict__ out) {
  __shared__ float E[16 * 129];
  __shared__ float Wt[24 * 129];
  int t = threadIdx.x;
  int bc0 = blockIdx.x * 16, pr0 = blockIdx.y * 24;
  int bcl = t & 15, prg = t >> 4;
  float acc[3] = {0.f, 0.f, 0.f};
  for (int k0 = 0; k0 < 4096; k0 += 128) {
    for (int e = t; e < 16 * 128; e += 128) {
      int r = e >> 7, cc = e & 127;
      E[r * 129 + cc] = g_enc[(bc0 + r) * 4096 + k0 + cc];
    }
    for (int e = t; e < 24 * 128; e += 128) {
      int r = e >> 7, cc = e & 127;
      Wt[r * 129 + cc] = ow[(pr0 + r) * 4096 + k0 + cc];
    }
    __syncthreads();
    for (int kkk = 0; kkk < 128; kkk++) {
      float ev = E[bcl * 129 + kkk];
      acc[0] += ev * Wt[(prg * 3 + 0) * 129 + kkk];
      acc[1] += ev * Wt[(prg * 3 + 1) * 129 + kkk];
      acc[2] += ev * Wt[(prg * 3 + 2) * 129 + kkk];
    }
    __syncthreads();
  }
  int bc = bc0 + bcl, b = bc >> 5, c = bc & 31;
  float sd = g_sd[bc], mu = g_mu[bc];
  for (int jj = 0; jj < 3; jj++) {
    int pr = pr0 + prg * 3 + jj;
    out[(b * 192 + pr) * 32 + c] = (acc[jj] + ob[pr]) * sd + mu;
  }
}

extern "C" void kernel_launch(void* const* d_in, const int* in_sizes, int n_in,
                              void* d_out, int out_size) {
  const float* x    = (const float*)d_in[0];
  const float* xw   = (const float*)d_in[4];
  const float* dw   = (const float*)d_in[5];
  const float* db   = (const float*)d_in[6];
  const float* Alog = (const float*)d_in[7];
  const float* Dp   = (const float*)d_in[8];
  const float* Kr   = (const float*)d_in[9];
  const float* Ki   = (const float*)d_in[10];
  const float* lng  = (const float*)d_in[11];
  const float* lnb  = (const float*)d_in[12];
  const float* ow   = (const float*)d_in[13];
  const float* ob   = (const float*)d_in[14];
  float* out = (float*)d_out;

  cudaFuncSetAttribute(kscan, cudaFuncAttributeMaxDynamicSharedMemorySize, (int)sizeof(SMS));
  cudaFuncSetAttribute(kDFT,  cudaFuncAttributeMaxDynamicSharedMemorySize, (int)sizeof(SMD));
  cudaFuncSetAttribute(kmix,  cudaFuncAttributeMaxDynamicSharedMemorySize, (int)sizeof(SMX));

  krepack<<<256, 256>>>(Kr, Ki);
  kA<<<BCn, 512>>>(x);
  for (int li = 0; li < 2; li++) {
    kscan<<<BCn, 512, sizeof(SMS)>>>(li, xw, dw, db, Alog, lng, lnb);
    kDFT<<<dim3(BCn, 8), 512, sizeof(SMD)>>>();
    kmix<<<dim3(BCn, 2), 256, sizeof(SMX)>>>(li, Dp);
  }
  khead<<<dim3(16, 8), 128>>>(ow, ob, out);
}

// round 16
// speedup vs baseline: 1.4730x; 1.4730x over previous
#include <cuda_runtime.h>
#include <math.h>

#define BCn 256

static __device__ float2 g_Xf[BCn*32*32*32];   // [m=(bc,p)][k][i]
static __device__ float2 g_Wt[2*32*32*32];     // [li][k][o][i]
static __device__ float2 g_G [BCn*32*32];      // [m][k]
static __device__ float  g_enc[BCn*4096];
static __device__ float  g_xn [BCn*4096];
static __device__ float  g_Cm [BCn*1024];      // [m][o]
static __device__ float  g_mu[BCn], g_sd[BCn];

struct SMS {
  float4 tw2[64*16];        // [dp][warp] = {cosA,-sinA,cosB,-sinB}, kkA=2w,kkB=2w+1
  float  su[64*32];         // [dp][i]  (dp=0 row: h_0)
  float  dv[64*32];         // [dp][i]  (dp=0 row: h_64)
  float  h[128*33];         // [d][s]
  float  enc[4096], xn[4096], del[4096];
  float  xw[72*129];
  float  dw[128*9];
  float  db[128], gg[128], bb[128];
  float  dbc[32*80];
};

__global__ void __launch_bounds__(512) kA(const float* __restrict__ x) {
  __shared__ float xs[512];
  __shared__ float red[34], red2[16];
  int t = threadIdx.x, bc = blockIdx.x, b = bc >> 5, c = bc & 31;
  float xv = x[(b * 512 + t) * 32 + c];
  float s1 = xv, s2 = xv * xv;
  for (int o = 16; o; o >>= 1) {
    s1 += __shfl_xor_sync(0xFFFFFFFFu, s1, o);
    s2 += __shfl_xor_sync(0xFFFFFFFFu, s2, o);
  }
  if ((t & 31) == 0) { red[t >> 5] = s1; red2[t >> 5] = s2; }
  __syncthreads();
  if (t == 0) {
    float a = 0.f, q = 0.f;
    for (int i = 0; i < 16; i++) { a += red[i]; q += red2[i]; }
    float mu = a * (1.f / 512.f);
    float sd = sqrtf(q * (1.f / 512.f) - mu * mu + 1e-5f);
    red[32] = mu; red[33] = sd;
    g_mu[bc] = mu; g_sd[bc] = sd;
  }
  __syncthreads();
  xs[t] = (xv - red[32]) / red[33];
  __syncthreads();
  for (int e = t; e < 4096; e += 512) {
    int p = e >> 7, d = e & 127, m = d >> 4, pl = d & 15;
    int t0 = p * 16 + pl;
    g_enc[bc * 4096 + e] = (t0 >= 7) ? xs[t0 - 7 + m] : 0.f;
  }
}

__global__ void krepack(const float* __restrict__ Kr, const float* __restrict__ Ki) {
  int idx = blockIdx.x * 256 + threadIdx.x;
  int k = idx & 31, o = (idx >> 5) & 31, i = (idx >> 10) & 31, li = idx >> 15;
  g_Wt[((li * 32 + k) * 32 + o) * 32 + i] = make_float2(Kr[idx], Ki[idx]);
}

__global__ void __launch_bounds__(512, 1) kscan(
    int li, const float* __restrict__ xw_g, const float* __restrict__ dw_g,
    const float* __restrict__ db_g, const float* __restrict__ Al_g,
    const float* __restrict__ lng, const float* __restrict__ lnb) {
  extern __shared__ __align__(16) unsigned char raw[];
  SMS* sm = reinterpret_cast<SMS*>(raw);
  int t = threadIdx.x, lane = t & 31, w = t >> 5, bc = blockIdx.x;

  for (int e = t; e < 1024; e += 512) {
    int dp = e >> 4, ww = e & 15;
    float sA, cA, sB, cB;
    sincospif((float)(dp * 2 * ww) * (1.0f / 64.0f), &sA, &cA);
    sincospif((float)(dp * (2 * ww + 1)) * (1.0f / 64.0f), &sB, &cB);
    sm->tw2[e] = make_float4(cA, -sA, cB, -sB);
  }
  for (int e = t; e < 9216; e += 512) {
    int r = e >> 7, d = e & 127;
    sm->xw[r * 129 + d] = xw_g[li * 9216 + e];
  }
  for (int e = t; e < 1024; e += 512) {
    int d = e >> 3, r = e & 7;
    sm->dw[d * 9 + r] = dw_g[li * 1024 + e];
  }
  if (t < 128) {
    sm->db[t] = db_g[li * 128 + t];
    sm->gg[t] = lng[li * 128 + t];
    sm->bb[t] = lnb[li * 128 + t];
  }
  for (int e = t; e < 4096; e += 512) sm->enc[e] = g_enc[bc * 4096 + e];
  __syncthreads();

  for (int pp = 0; pp < 2; pp++) {
    int p = w * 2 + pp;
    float v[4], s = 0.f, q = 0.f;
    for (int j = 0; j < 4; j++) {
      v[j] = sm->enc[p * 128 + lane + 32 * j];
      s += v[j]; q += v[j] * v[j];
    }
    for (int o = 16; o; o >>= 1) {
      s += __shfl_xor_sync(0xFFFFFFFFu, s, o);
      q += __shfl_xor_sync(0xFFFFFFFFu, q, o);
    }
    float mu = s * (1.f / 128.f);
    float rs = rsqrtf(q * (1.f / 128.f) - mu * mu + 1e-5f);
    for (int j = 0; j < 4; j++) {
      int d = lane + 32 * j;
      sm->xn[p * 128 + d] = (v[j] - mu) * rs * sm->gg[d] + sm->bb[d];
    }
  }
  __syncthreads();

  {
    int p = t >> 4, rt = t & 15;
    float a0 = 0, a1 = 0, a2 = 0, a3 = 0, a4 = 0;
    const float* xp = &sm->xn[p * 128];
    for (int d = 0; d < 128; d++) {
      float xv = xp[d];
      a0 += xv * sm->xw[rt * 129 + d];
      a1 += xv * sm->xw[(rt + 16) * 129 + d];
      a2 += xv * sm->xw[(rt + 32) * 129 + d];
      a3 += xv * sm->xw[(rt + 48) * 129 + d];
      if (rt < 8) a4 += xv * sm->xw[(rt + 64) * 129 + d];
    }
    sm->dbc[p * 80 + rt] = a0;
    sm->dbc[p * 80 + rt + 16] = a1;
    sm->dbc[p * 80 + rt + 32] = a2;
    sm->dbc[p * 80 + rt + 48] = a3;
    if (rt < 8) sm->dbc[p * 80 + rt + 64] = a4;
  }
  __syncthreads();

  {
    int p = t >> 4, d0 = (t & 15) * 8;
    for (int d = d0; d < d0 + 8; d++) {
      float a = sm->db[d];
      for (int r = 0; r < 8; r++) a += sm->dbc[p * 80 + r] * sm->dw[d * 9 + r];
      sm->del[p * 128 + d] = (a > 20.f) ? a : log1pf(__expf(a));
    }
    int s2 = (t & 15) * 2;
    g_Cm[bc * 1024 + p * 32 + s2]     = sm->dbc[p * 80 + 40 + s2];
    g_Cm[bc * 1024 + p * 32 + s2 + 1] = sm->dbc[p * 80 + 40 + s2 + 1];
  }
  __syncthreads();

  // scan (thread: d = t>>2, 8 states) + DFT (lane = i, warp = k-pair)
  int dd = t >> 2, s0 = (t & 3) * 8;
  float A[8], hreg[8];
  for (int q = 0; q < 8; q++) {
    A[q] = -__expf(Al_g[li * 4096 + dd * 32 + s0 + q]);
    hreg[q] = 0.f;
  }
  int kkA = 2 * w;

  for (int p = 0; p < 32; p++) {
    float dl = sm->del[p * 128 + dd];
    float bx = dl * sm->xn[p * 128 + dd];
#pragma unroll
    for (int q = 0; q < 8; q++) {
      hreg[q] = __expf(dl * A[q]) * hreg[q] + bx * sm->dbc[p * 80 + 8 + s0 + q];
      sm->h[dd * 33 + s0 + q] = hreg[q];
    }
    __syncthreads();
#pragma unroll
    for (int e0 = 0; e0 < 4; e0++) {
      int e = t + 512 * e0;
      int dp = e >> 5, i = e & 31;
      if (dp == 0) {
        sm->su[i] = sm->h[i];
        sm->dv[i] = sm->h[64 * 33 + i];
      } else {
        float a = sm->h[dp * 33 + i], b2 = sm->h[(128 - dp) * 33 + i];
        sm->su[dp * 32 + i] = a + b2;
        sm->dv[dp * 32 + i] = a - b2;
      }
    }
    __syncthreads();
    float dv0 = sm->dv[lane];
    float arA = dv0, arB = -dv0, aiA = 0.f, aiB = 0.f;
#pragma unroll 8
    for (int dp = 0; dp < 64; dp++) {
      float4 tw = sm->tw2[dp * 16 + w];
      float suv = sm->su[dp * 32 + lane];
      float dvv = sm->dv[dp * 32 + lane];
      arA += suv * tw.x; aiA += dvv * tw.y;
      arB += suv * tw.z; aiB += dvv * tw.w;
    }
    float2* base = &g_Xf[((bc * 32 + p) * 32) * 32];
    base[kkA * 32 + lane]       = make_float2(arA, aiA);
    base[(kkA + 1) * 32 + lane] = make_float2(arB, aiB);
  }
  for (int e = t; e < 4096; e += 512) g_xn[bc * 4096 + e] = sm->xn[e];
}

// V[m,i,k] = sum_o Cm[m,o] * W[k,o,i];  G[m,k] = sum_i V[m,i,k] * X[m,k,i]
__global__ void __launch_bounds__(128) kGV(int li) {
  __shared__ float  Cm_s[32 * 128];   // [o][m]
  __shared__ float2 Wk_s[32 * 32];    // [o][i]
  int t = threadIdx.x;
  int mbase = blockIdx.x * 128;
  int k = blockIdx.y;

  for (int e = t; e < 4096; e += 128) {
    int m = e >> 5, o = e & 31;
    Cm_s[o * 128 + m] = g_Cm[(mbase + m) * 32 + o];
  }
  const float2* wsrc = &g_Wt[((li * 32 + k) * 32) * 32];
  for (int e = t; e < 1024; e += 128) Wk_s[e] = wsrc[e];
  __syncthreads();

  int mgrp = t >> 2, igrp = t & 3;
  int m0 = mgrp * 4, i0 = igrp * 8;
  float2 V[4][8];
#pragma unroll
  for (int a = 0; a < 4; a++)
#pragma unroll
    for (int b = 0; b < 8; b++) V[a][b] = make_float2(0.f, 0.f);

  for (int o = 0; o < 32; o++) {
    float4 cm4 = *reinterpret_cast<const float4*>(&Cm_s[o * 128 + m0]);
    const float2* wr = &Wk_s[o * 32 + i0];
    float2 wv[8];
#pragma unroll
    for (int b = 0; b < 8; b++) wv[b] = wr[b];
    float cms[4] = {cm4.x, cm4.y, cm4.z, cm4.w};
#pragma unroll
    for (int a = 0; a < 4; a++) {
      float c = cms[a];
#pragma unroll
      for (int b = 0; b < 8; b++) {
        V[a][b].x += c * wv[b].x;
        V[a][b].y += c * wv[b].y;
      }
    }
  }

#pragma unroll
  for (int a = 0; a < 4; a++) {
    int m = mbase + m0 + a;
    const float2* xp = &g_Xf[(m * 32 + k) * 32 + i0];
    float gx = 0.f, gy = 0.f;
#pragma unroll
    for (int b = 0; b < 8; b++) {
      float2 xf = xp[b];
      gx += xf.x * V[a][b].x - xf.y * V[a][b].y;
      gy += xf.x * V[a][b].y + xf.y * V[a][b].x;
    }
    gx += __shfl_xor_sync(0xFFFFFFFFu, gx, 1);
    gy += __shfl_xor_sync(0xFFFFFFFFu, gy, 1);
    gx += __shfl_xor_sync(0xFFFFFFFFu, gx, 2);
    gy += __shfl_xor_sync(0xFFFFFFFFu, gy, 2);
    if (igrp == 0) g_G[m * 32 + k] = make_float2(gx, gy);
  }
}

__global__ void __launch_bounds__(256) kEpi(int li, const float* __restrict__ Dp_g) {
  __shared__ float2 G_s[32 * 33];
  __shared__ float2 trigH[65 * 33];
  __shared__ float  dpv[128];
  int t = threadIdx.x, bc = blockIdx.x;

  for (int e = t; e < 2145; e += 256) {
    int d = e / 33, k = e % 33;
    if (k < 32) {
      float sv, cv;
      sincospif((float)(d * k) * (1.0f / 64.0f), &sv, &cv);
      trigH[d * 33 + k] = make_float2(cv, -sv);
    }
  }
  for (int e = t; e < 1024; e += 256) {
    int p = e >> 5, kk = e & 31;
    G_s[p * 33 + kk] = g_G[(bc * 32 + p) * 32 + kk];
  }
  if (t < 128) dpv[t] = Dp_g[li * 128 + t];
  __syncthreads();

  int p = t >> 3, j = t & 7;
  float g0 = G_s[p * 33].x;
  for (int m = 0; m < 8; m++) {
    int dp = j * 8 + m;
    float accC = g0, accS = 0.f;
    for (int k = 1; k < 32; k++) {
      float2 gk = G_s[p * 33 + k];
      float2 tp = trigH[dp * 33 + k];
      accC += 2.f * gk.x * tp.x;
      accS += 2.f * gk.y * tp.y;
    }
    int e = p * 128 + dp;
    g_enc[bc * 4096 + e] += (accC + accS) * (1.f / 128.f) + dpv[dp] * g_xn[bc * 4096 + e];
    if (dp >= 1) {
      int d2 = 128 - dp, e2 = p * 128 + d2;
      g_enc[bc * 4096 + e2] += (accC - accS) * (1.f / 128.f) + dpv[d2] * g_xn[bc * 4096 + e2];
    }
  }
  if (j == 0) {
    float acc = g0;
    for (int k = 1; k < 32; k++)
      acc += 2.f * G_s[p * 33 + k].x * ((k & 1) ? -1.f : 1.f);
    int e = p * 128 + 64;
    g_enc[bc * 4096 + e] += acc * (1.f / 128.f) + dpv[64] * g_xn[bc * 4096 + e];
  }
}

__global__ void __launch_bounds__(128) khead(const float* __restrict__ ow,
                                             const float* __restrict__ ob,
                                             float* __restrict__ out) {
  __shared__ float E[16 * 129];
  __shared__ float Wt[24 * 129];
  int t = threadIdx.x;
  int bc0 = blockIdx.x * 16, pr0 = blockIdx.y * 24;
  int bcl = t & 15, prg = t >> 4;
  float acc[3] = {0.f, 0.f, 0.f};
  for (int k0 = 0; k0 < 4096; k0 += 128) {
    for (int e = t; e < 16 * 128; e += 128) {
      int r = e >> 7, cc = e & 127;
      E[r * 129 + cc] = g_enc[(bc0 + r) * 4096 + k0 + cc];
    }
    for (int e = t; e < 24 * 128; e += 128) {
      int r = e >> 7, cc = e & 127;
      Wt[r * 129 + cc] = ow[(pr0 + r) * 4096 + k0 + cc];
    }
    __syncthreads();
    for (int kkk = 0; kkk < 128; kkk++) {
      float ev = E[bcl * 129 + kkk];
      acc[0] += ev * Wt[(prg * 3 + 0) * 129 + kkk];
      acc[1] += ev * Wt[(prg * 3 + 1) * 129 + kkk];
      acc[2] += ev * Wt[(prg * 3 + 2) * 129 + kkk];
    }
    __syncthreads();
  }
  int bc = bc0 + bcl, b = bc >> 5, c = bc & 31;
  float sd = g_sd[bc], mu = g_mu[bc];
  for (int jj = 0; jj < 3; jj++) {
    int pr = pr0 + prg * 3 + jj;
    out[(b * 192 + pr) * 32 + c] = (acc[jj] + ob[pr]) * sd + mu;
  }
}

extern "C" void kernel_launch(void* const* d_in, const int* in_sizes, int n_in,
                              void* d_out, int out_size) {
  const float* x    = (const float*)d_in[0];
  const float* xw   = (const float*)d_in[4];
  const float* dw   = (const float*)d_in[5];
  const float* db   = (const float*)d_in[6];
  const float* Alog = (const float*)d_in[7];
  const float* Dp   = (const float*)d_in[8];
  const float* Kr   = (const float*)d_in[9];
  const float* Ki   = (const float*)d_in[10];
  const float* lng  = (const float*)d_in[11];
  const float* lnb  = (const float*)d_in[12];
  const float* ow   = (const float*)d_in[13];
  const float* ob   = (const float*)d_in[14];
  float* out = (float*)d_out;

  cudaFuncSetAttribute(kscan, cudaFuncAttributeMaxDynamicSharedMemorySize, (int)sizeof(SMS));

  krepack<<<256, 256>>>(Kr, Ki);
  kA<<<BCn, 512>>>(x);
  for (int li = 0; li < 2; li++) {
    kscan<<<BCn, 512, sizeof(SMS)>>>(li, xw, dw, db, Alog, lng, lnb);
    kGV<<<dim3(64, 32), 128>>>(li);
    kEpi<<<BCn, 256>>>(li, Dp);
  }
  khead<<<dim3(16, 8), 128>>>(ow, ob, out);
}